// round 7
// baseline (speedup 1.0000x reference)
#include <cuda_runtime.h>
#include <cuda_fp16.h>
#include <cstdint>

constexpr int NA = 1024, NB = 1024, DD = 512, KK = 256;
constexpr int XROWS = NA + NB;

// Device scratch (fp16 split: h + l, residual 2^-22)
__device__ __half g_Xh[XROWS * DD];
__device__ __half g_Xl[NB * DD];        // lo part only needed for b rows (mask sign)
__device__ __half g_Fh[KK * DD];
__device__ __half g_Fl[KK * DD];
__device__ __half g_Ph[NA * KK];
__device__ __half g_Mb[NB * KK];

// ---------------------------------------------------------------------------
// PTX helpers
// ---------------------------------------------------------------------------
__device__ __forceinline__ uint32_t smem_u32(const void* p) {
    uint32_t r;
    asm("{ .reg .u64 t; cvta.to.shared.u64 t, %1; cvt.u32.u64 %0, t; }" : "=r"(r) : "l"(p));
    return r;
}
__device__ __forceinline__ void cp16(uint32_t dst, const void* src) {
    asm volatile("cp.async.cg.shared.global [%0], [%1], 16;" :: "r"(dst), "l"(src) : "memory");
}
__device__ __forceinline__ void cp_commit() { asm volatile("cp.async.commit_group;" ::: "memory"); }
__device__ __forceinline__ void cp_wait1()  { asm volatile("cp.async.wait_group 1;" ::: "memory"); }
__device__ __forceinline__ void cp_wait0()  { asm volatile("cp.async.wait_group 0;" ::: "memory"); }

__device__ __forceinline__ void ldm_x4(uint32_t* r, uint32_t addr) {
    asm volatile("ldmatrix.sync.aligned.m8n8.x4.shared.b16 {%0,%1,%2,%3}, [%4];"
                 : "=r"(r[0]), "=r"(r[1]), "=r"(r[2]), "=r"(r[3]) : "r"(addr));
}
__device__ __forceinline__ void mma_f16(float* d, const uint32_t* a, const uint32_t* b) {
    asm volatile(
        "mma.sync.aligned.m16n8k16.row.col.f32.f16.f16.f32 "
        "{%0,%1,%2,%3}, {%4,%5,%6,%7}, {%8,%9}, {%0,%1,%2,%3};"
        : "+f"(d[0]), "+f"(d[1]), "+f"(d[2]), "+f"(d[3])
        : "r"(a[0]), "r"(a[1]), "r"(a[2]), "r"(a[3]), "r"(b[0]), "r"(b[1]));
}

// row stride 144B: consecutive rows shift 16B mod 128 -> ldmatrix conflict-free
constexpr uint32_t TSTR = 144;
constexpr uint32_t ARR  = 64 * TSTR;   // 9216 bytes per 64-row tile array

__device__ __forceinline__ uint32_t a_addr(uint32_t base, int row0, int lane, int koff) {
    return base + (uint32_t)(row0 + (lane & 15)) * TSTR + (uint32_t)koff + ((lane >> 4) << 4);
}
__device__ __forceinline__ uint32_t b_addr(uint32_t base, int row0, int lane, int koff) {
    return base + (uint32_t)(row0 + (lane & 7) + ((lane >> 4) << 3)) * TSTR
                + (uint32_t)koff + (((lane >> 3) & 1) << 4);
}

// ---------------------------------------------------------------------------
// Kernel 0: split fp32 -> (h, l) fp16. Exactly 2 independent float4/thread.
// ---------------------------------------------------------------------------
constexpr int CV_NT  = 147456;              // 576 blocks x 256 threads
constexpr int CV_XN4 = XROWS * DD / 4;      // 262144
// total items = 294912 = 2 * CV_NT exactly

__global__ __launch_bounds__(256) void convert_kernel(
    const float* __restrict__ a, const float* __restrict__ b, const float* __restrict__ feats)
{
    const int t = blockIdx.x * 256 + threadIdx.x;

    float4 v[2];
    int i4[2];
#pragma unroll
    for (int k = 0; k < 2; k++) {
        i4[k] = t + k * CV_NT;
        if (i4[k] < CV_XN4) {
            const int base = i4[k] * 4;
            v[k] = (base < NA * DD) ? *reinterpret_cast<const float4*>(a + base)
                                    : *reinterpret_cast<const float4*>(b + base - NA * DD);
        } else {
            v[k] = *reinterpret_cast<const float4*>(feats + (i4[k] - CV_XN4) * 4);
        }
    }
#pragma unroll
    for (int k = 0; k < 2; k++) {
        const float xs[4] = {v[k].x, v[k].y, v[k].z, v[k].w};
        __half hs[4], ls[4];
#pragma unroll
        for (int i = 0; i < 4; i++) {
            hs[i] = __float2half(xs[i]);
            ls[i] = __float2half(xs[i] - __half2float(hs[i]));
        }
        const __half2 h01(hs[0], hs[1]), h23(hs[2], hs[3]);
        const __half2 l01(ls[0], ls[1]), l23(ls[2], ls[3]);
        if (i4[k] < CV_XN4) {
            const int base = i4[k] * 4;
            *reinterpret_cast<__half2*>(g_Xh + base)     = h01;
            *reinterpret_cast<__half2*>(g_Xh + base + 2) = h23;
            if (base >= NA * DD) {   // lo part only for b rows
                *reinterpret_cast<__half2*>(g_Xl + base - NA * DD)     = l01;
                *reinterpret_cast<__half2*>(g_Xl + base - NA * DD + 2) = l23;
            }
        } else {
            const int base = (i4[k] - CV_XN4) * 4;
            *reinterpret_cast<__half2*>(g_Fh + base)     = h01;
            *reinterpret_cast<__half2*>(g_Fh + base + 2) = h23;
            *reinterpret_cast<__half2*>(g_Fl + base)     = l01;
            *reinterpret_cast<__half2*>(g_Fl + base + 2) = l23;
        }
    }
}

// ---------------------------------------------------------------------------
// Stage 1: C[2048x256] = X · F^T
//   a rows: single product Xh·Fh        (P values: 1e-4 norm impact)
//   b rows: XhFh + XhFl + XlFh          (mask sign: residual 2^-22)
// Tile 64x64, 512 threads (16 warps, warp tile 16x16), k-chunk 64,
// 3 smem buffers, depth-2 cp.async, 1 sync/chunk. grid (4, 32).
// ---------------------------------------------------------------------------
constexpr uint32_t S1_BUF = 4 * ARR;    // Xh, Xl, Fh, Fl
constexpr int S1_SMEM = 3 * S1_BUF;     // 110592

__global__ __launch_bounds__(512) void stage1_mma()
{
    extern __shared__ char dsm[];
    const uint32_t sb = smem_u32(dsm);

    const int tid = threadIdx.x;
    const int lane = tid & 31;
    const int wid = tid >> 5;
    const int wm = wid & 3;          // 4 warp rows x 16
    const int wn = wid >> 2;         // 4 warp cols x 16

    const int m0 = blockIdx.y * 64;
    const int n0 = blockIdx.x * 64;
    const bool isA = (m0 < NA);

    const __half* pXh = g_Xh + (size_t)m0 * DD;
    const __half* pXl = g_Xl + (size_t)(isA ? 0 : m0 - NA) * DD;
    const __half* pFh = g_Fh + (size_t)n0 * DD;
    const __half* pFl = g_Fl + (size_t)n0 * DD;

    const int lr = tid >> 3, ls = tid & 7;   // 64 rows x 8 sixteen-byte slots
    auto load_chunk = [&](int ch, uint32_t buf) {
        const size_t off = (size_t)lr * DD + ch * 64 + ls * 8;
        const uint32_t sm = buf + (uint32_t)lr * TSTR + (uint32_t)(ls << 4);
        cp16(sm + 0 * ARR, pXh + off);
        cp16(sm + 2 * ARR, pFh + off);
        if (!isA) {
            cp16(sm + 1 * ARR, pXl + off);
            cp16(sm + 3 * ARR, pFl + off);
        }
        cp_commit();
    };

    constexpr int NCH = DD / 64;   // 8
    load_chunk(0, sb);
    load_chunk(1, sb + S1_BUF);

    float acc[2][4] = {};

    for (int ch = 0; ch < NCH; ch++) {
        if (ch + 1 < NCH) cp_wait1(); else cp_wait0();
        __syncthreads();
        if (ch + 2 < NCH) load_chunk(ch + 2, sb + (uint32_t)((ch + 2) % 3) * S1_BUF);

        const uint32_t bb = sb + (uint32_t)(ch % 3) * S1_BUF;
#pragma unroll
        for (int ks = 0; ks < 4; ks++) {
            const int koff = ks * 32;
            uint32_t ah[4], fh[4];
            ldm_x4(ah, a_addr(bb + 0 * ARR, wm * 16, lane, koff));
            ldm_x4(fh, b_addr(bb + 2 * ARR, wn * 16, lane, koff));
            if (isA) {
                mma_f16(acc[0], ah, &fh[0]);
                mma_f16(acc[1], ah, &fh[2]);
            } else {
                uint32_t al[4], fl[4];
                ldm_x4(al, a_addr(bb + 1 * ARR, wm * 16, lane, koff));
                ldm_x4(fl, b_addr(bb + 3 * ARR, wn * 16, lane, koff));
#pragma unroll
                for (int nt = 0; nt < 2; nt++) {
                    mma_f16(acc[nt], ah, &fh[nt * 2]);
                    mma_f16(acc[nt], ah, &fl[nt * 2]);
                    mma_f16(acc[nt], al, &fh[nt * 2]);
                }
            }
        }
    }

    // Epilogue: a-rows -> Ph = fp16(relu(v)); b-rows -> Mb = fp16(v<=0)
#pragma unroll
    for (int nt = 0; nt < 2; nt++)
#pragma unroll
        for (int h = 0; h < 2; h++) {
            const int grow = m0 + wm * 16 + (lane >> 2) + h * 8;
            const int col  = n0 + wn * 16 + nt * 8 + (lane & 3) * 2;
            const float v0 = acc[nt][h * 2 + 0];
            const float v1 = acc[nt][h * 2 + 1];
            if (isA) {
                const size_t idx = (size_t)grow * KK + col;
                *reinterpret_cast<__half2*>(g_Ph + idx) =
                    __half2(__float2half(fmaxf(v0, 0.0f)), __float2half(fmaxf(v1, 0.0f)));
            } else {
                const size_t idx = (size_t)(grow - NA) * KK + col;
                *reinterpret_cast<__half2*>(g_Mb + idx) =
                    __half2(__float2half(v0 <= 0.0f ? 1.0f : 0.0f),
                            __float2half(v1 <= 0.0f ? 1.0f : 0.0f));
            }
        }
}

// ---------------------------------------------------------------------------
// Stage 2: out[1024x1024] = Ph · Mb^T (fp16, fp32 accum)
// Tile 64x64, 512 threads (16 warps, warp tile 16x16), k-chunk 64,
// 3 buffers, 1 sync/chunk. grid (16, 16).
// ---------------------------------------------------------------------------
constexpr uint32_t S2_BUF = 2 * ARR;    // Ph, Mb
constexpr int S2_SMEM = 3 * S2_BUF;     // 55296

__global__ __launch_bounds__(512) void stage2_mma(float* __restrict__ out)
{
    extern __shared__ char dsm[];
    const uint32_t sb = smem_u32(dsm);

    const int tid = threadIdx.x;
    const int lane = tid & 31;
    const int wid = tid >> 5;
    const int wm = wid & 3;
    const int wn = wid >> 2;

    const int i0 = blockIdx.y * 64;
    const int j0 = blockIdx.x * 64;

    const __half* pPh = g_Ph + (size_t)i0 * KK;
    const __half* pMb = g_Mb + (size_t)j0 * KK;

    const int lr = tid >> 3, ls = tid & 7;
    auto load_chunk = [&](int ch, uint32_t buf) {
        const size_t off = (size_t)lr * KK + ch * 64 + ls * 8;
        const uint32_t sm = buf + (uint32_t)lr * TSTR + (uint32_t)(ls << 4);
        cp16(sm + 0 * ARR, pPh + off);
        cp16(sm + 1 * ARR, pMb + off);
        cp_commit();
    };

    constexpr int NCH = KK / 64;   // 4
    load_chunk(0, sb);
    load_chunk(1, sb + S2_BUF);

    float acc[2][4] = {};

    for (int ch = 0; ch < NCH; ch++) {
        if (ch + 1 < NCH) cp_wait1(); else cp_wait0();
        __syncthreads();
        if (ch + 2 < NCH) load_chunk(ch + 2, sb + (uint32_t)((ch + 2) % 3) * S2_BUF);

        const uint32_t bb = sb + (uint32_t)(ch % 3) * S2_BUF;
#pragma unroll
        for (int ks = 0; ks < 4; ks++) {
            const int koff = ks * 32;
            uint32_t ph[4], mb[4];
            ldm_x4(ph, a_addr(bb + 0 * ARR, wm * 16, lane, koff));
            ldm_x4(mb, b_addr(bb + 1 * ARR, wn * 16, lane, koff));
            mma_f16(acc[0], ph, &mb[0]);
            mma_f16(acc[1], ph, &mb[2]);
        }
    }

#pragma unroll
    for (int nt = 0; nt < 2; nt++)
#pragma unroll
        for (int h = 0; h < 2; h++) {
            const int row = i0 + wm * 16 + (lane >> 2) + h * 8;
            const int col = j0 + wn * 16 + nt * 8 + (lane & 3) * 2;
            *reinterpret_cast<float2*>(out + (size_t)row * NB + col) =
                make_float2(acc[nt][h * 2 + 0], acc[nt][h * 2 + 1]);
        }
}

// ---------------------------------------------------------------------------
extern "C" void kernel_launch(void* const* d_in, const int* in_sizes, int n_in,
                              void* d_out, int out_size)
{
    const float* a     = (const float*)d_in[0];
    const float* b     = (const float*)d_in[1];
    const float* feats = (const float*)d_in[2];
    float* out = (float*)d_out;
    (void)in_sizes; (void)n_in; (void)out_size;

    cudaFuncSetAttribute(stage1_mma, cudaFuncAttributeMaxDynamicSharedMemorySize, S1_SMEM);
    cudaFuncSetAttribute(stage2_mma, cudaFuncAttributeMaxDynamicSharedMemorySize, S2_SMEM);

    convert_kernel<<<576, 256>>>(a, b, feats);
    stage1_mma<<<dim3(4, 32), 512, S1_SMEM>>>();
    stage2_mma<<<dim3(16, 16), 512, S2_SMEM>>>(out);
}

// round 8
// speedup vs baseline: 1.1199x; 1.1199x over previous
#include <cuda_runtime.h>
#include <cuda_fp16.h>
#include <cstdint>

constexpr int NA = 1024, NB = 1024, DD = 512, KK = 256;
constexpr int XROWS = NA + NB;

// Device scratch (fp16 split; lo only where mask sign needs it)
__device__ __half g_Xh[XROWS * DD];
__device__ __half g_Xl[NB * DD];
__device__ __half g_Fh[KK * DD];
__device__ __half g_Fl[KK * DD];
__device__ __half g_Ph[NA * KK];
__device__ __half g_Mb[NB * KK];

// ---------------------------------------------------------------------------
// PTX helpers
// ---------------------------------------------------------------------------
__device__ __forceinline__ uint32_t smem_u32(const void* p) {
    uint32_t r;
    asm("{ .reg .u64 t; cvta.to.shared.u64 t, %1; cvt.u32.u64 %0, t; }" : "=r"(r) : "l"(p));
    return r;
}
__device__ __forceinline__ void cp16(uint32_t dst, const void* src) {
    asm volatile("cp.async.cg.shared.global [%0], [%1], 16;" :: "r"(dst), "l"(src) : "memory");
}
__device__ __forceinline__ void cp_commit() { asm volatile("cp.async.commit_group;" ::: "memory"); }
__device__ __forceinline__ void cp_wait1()  { asm volatile("cp.async.wait_group 1;" ::: "memory"); }
__device__ __forceinline__ void cp_wait0()  { asm volatile("cp.async.wait_group 0;" ::: "memory"); }

__device__ __forceinline__ void ldm_x4(uint32_t* r, uint32_t addr) {
    asm volatile("ldmatrix.sync.aligned.m8n8.x4.shared.b16 {%0,%1,%2,%3}, [%4];"
                 : "=r"(r[0]), "=r"(r[1]), "=r"(r[2]), "=r"(r[3]) : "r"(addr));
}
__device__ __forceinline__ void mma_f16(float* d, const uint32_t* a, const uint32_t* b) {
    asm volatile(
        "mma.sync.aligned.m16n8k16.row.col.f32.f16.f16.f32 "
        "{%0,%1,%2,%3}, {%4,%5,%6,%7}, {%8,%9}, {%0,%1,%2,%3};"
        : "+f"(d[0]), "+f"(d[1]), "+f"(d[2]), "+f"(d[3])
        : "r"(a[0]), "r"(a[1]), "r"(a[2]), "r"(a[3]), "r"(b[0]), "r"(b[1]));
}

constexpr uint32_t TSTR = 144;         // 16B shift per row mod 128 -> conflict-free
constexpr uint32_t ARR  = 64 * TSTR;   // 9216 bytes / 64-row array

__device__ __forceinline__ uint32_t a_addr(uint32_t base, int row0, int lane, int koff) {
    return base + (uint32_t)(row0 + (lane & 15)) * TSTR + (uint32_t)koff + ((lane >> 4) << 4);
}
__device__ __forceinline__ uint32_t b_addr(uint32_t base, int row0, int lane, int koff) {
    return base + (uint32_t)(row0 + (lane & 7) + ((lane >> 4) << 3)) * TSTR
                + (uint32_t)koff + (((lane >> 3) & 1) << 4);
}

// ---------------------------------------------------------------------------
// Kernel 0 (v4): region-uniform split, 8 floats/thread, 16B stores.
//   blocks [0,256):  a rows  -> Xh only
//   blocks [256,512): b rows -> Xh + Xl
//   blocks [512,576): feats  -> Fh + Fl
// ---------------------------------------------------------------------------
__device__ __forceinline__ uint32_t hpack(float x, float y) {
    __half2 t = __float22half2_rn(make_float2(x, y));
    return *reinterpret_cast<uint32_t*>(&t);
}
__device__ __forceinline__ uint4 hi4(const float4& v0, const float4& v1) {
    return make_uint4(hpack(v0.x, v0.y), hpack(v0.z, v0.w),
                      hpack(v1.x, v1.y), hpack(v1.z, v1.w));
}
__device__ __forceinline__ uint4 lo4(const float4& v0, const float4& v1) {
    float l[8];
    const float xs[8] = {v0.x, v0.y, v0.z, v0.w, v1.x, v1.y, v1.z, v1.w};
#pragma unroll
    for (int i = 0; i < 8; i++)
        l[i] = xs[i] - __half2float(__float2half(xs[i]));
    return make_uint4(hpack(l[0], l[1]), hpack(l[2], l[3]),
                      hpack(l[4], l[5]), hpack(l[6], l[7]));
}

__global__ __launch_bounds__(256) void convert_kernel(
    const float* __restrict__ a, const float* __restrict__ b, const float* __restrict__ feats)
{
    const int bid = blockIdx.x, tid = threadIdx.x;
    if (bid < 256) {                       // a rows: hi only
        const int base = (bid * 256 + tid) * 8;
        const float4 v0 = *reinterpret_cast<const float4*>(a + base);
        const float4 v1 = *reinterpret_cast<const float4*>(a + base + 4);
        *reinterpret_cast<uint4*>(g_Xh + base) = hi4(v0, v1);
    } else if (bid < 512) {                // b rows: hi + lo
        const int base = ((bid - 256) * 256 + tid) * 8;
        const float4 v0 = *reinterpret_cast<const float4*>(b + base);
        const float4 v1 = *reinterpret_cast<const float4*>(b + base + 4);
        *reinterpret_cast<uint4*>(g_Xh + NA * DD + base) = hi4(v0, v1);
        *reinterpret_cast<uint4*>(g_Xl + base)           = lo4(v0, v1);
    } else {                               // feats: hi + lo
        const int base = ((bid - 512) * 256 + tid) * 8;
        const float4 v0 = *reinterpret_cast<const float4*>(feats + base);
        const float4 v1 = *reinterpret_cast<const float4*>(feats + base + 4);
        *reinterpret_cast<uint4*>(g_Fh + base) = hi4(v0, v1);
        *reinterpret_cast<uint4*>(g_Fl + base) = lo4(v0, v1);
    }
}

// ---------------------------------------------------------------------------
// Stage 1: C[2048x256] = X · F^T
//   a rows: Xh·Fh ;  b rows: XhFh + XhFl + XlFh
// Tile 64x64, 256 threads (8 warps, warp tile 16x32), k-chunk 64,
// 3 smem buffers, 1 sync/chunk. grid (4, 32).
// ---------------------------------------------------------------------------
constexpr uint32_t S1_BUF = 4 * ARR;    // arrays: 0=Xh 1=Xl 2=Fh 3=Fl
constexpr int S1_SMEM = 3 * S1_BUF;     // 110592

__global__ __launch_bounds__(256) void stage1_mma()
{
    extern __shared__ char dsm[];
    const uint32_t sb = smem_u32(dsm);

    const int tid = threadIdx.x;
    const int lane = tid & 31;
    const int wid = tid >> 5;
    const int wm = wid & 3;          // 4 warp rows x 16
    const int wn = wid >> 2;         // 2 warp cols x 32

    const int m0 = blockIdx.y * 64;
    const int n0 = blockIdx.x * 64;
    const bool isA = (m0 < NA);

    const __half* pXh = g_Xh + (size_t)m0 * DD;
    const __half* pXl = g_Xl + (size_t)(isA ? 0 : m0 - NA) * DD;
    const __half* pFh = g_Fh + (size_t)n0 * DD;
    const __half* pFl = g_Fl + (size_t)n0 * DD;

    const int lr = tid >> 3, ls = tid & 7;   // 32 rows x 8 slots per pass
    auto load_chunk = [&](int ch, uint32_t buf) {
        const int d0 = ch * 64;
#pragma unroll
        for (int pass = 0; pass < 2; pass++) {
            const int r = lr + pass * 32;
            const size_t off = (size_t)r * DD + d0 + ls * 8;
            const uint32_t sm = buf + (uint32_t)r * TSTR + (uint32_t)(ls << 4);
            cp16(sm + 0 * ARR, pXh + off);
            cp16(sm + 2 * ARR, pFh + off);
            if (!isA) {
                cp16(sm + 1 * ARR, pXl + off);
                cp16(sm + 3 * ARR, pFl + off);
            }
        }
        cp_commit();
    };

    constexpr int NCH = DD / 64;   // 8
    load_chunk(0, sb);
    load_chunk(1, sb + S1_BUF);

    float acc[4][4] = {};

    for (int ch = 0; ch < NCH; ch++) {
        if (ch + 1 < NCH) cp_wait1(); else cp_wait0();
        __syncthreads();
        if (ch + 2 < NCH) load_chunk(ch + 2, sb + (uint32_t)((ch + 2) % 3) * S1_BUF);

        const uint32_t bb = sb + (uint32_t)(ch % 3) * S1_BUF;
#pragma unroll
        for (int ks = 0; ks < 4; ks++) {
            const int koff = ks * 32;
            uint32_t ah[4], fh[2][4];
            ldm_x4(ah, a_addr(bb + 0 * ARR, wm * 16, lane, koff));
#pragma unroll
            for (int p = 0; p < 2; p++)
                ldm_x4(fh[p], b_addr(bb + 2 * ARR, wn * 32 + p * 16, lane, koff));
            if (isA) {
#pragma unroll
                for (int nt = 0; nt < 4; nt++)
                    mma_f16(acc[nt], ah, &fh[nt >> 1][(nt & 1) * 2]);
            } else {
                uint32_t al[4], fl[2][4];
                ldm_x4(al, a_addr(bb + 1 * ARR, wm * 16, lane, koff));
#pragma unroll
                for (int p = 0; p < 2; p++)
                    ldm_x4(fl[p], b_addr(bb + 3 * ARR, wn * 32 + p * 16, lane, koff));
#pragma unroll
                for (int nt = 0; nt < 4; nt++) {
                    const uint32_t* bh = &fh[nt >> 1][(nt & 1) * 2];
                    const uint32_t* bl = &fl[nt >> 1][(nt & 1) * 2];
                    mma_f16(acc[nt], ah, bh);
                    mma_f16(acc[nt], ah, bl);
                    mma_f16(acc[nt], al, bh);
                }
            }
        }
    }

    // Epilogue: a-rows -> Ph = fp16(relu(v)); b-rows -> Mb = fp16(v<=0)
#pragma unroll
    for (int nt = 0; nt < 4; nt++)
#pragma unroll
        for (int h = 0; h < 2; h++) {
            const int grow = m0 + wm * 16 + (lane >> 2) + h * 8;
            const int col  = n0 + wn * 32 + nt * 8 + (lane & 3) * 2;
            const float v0 = acc[nt][h * 2 + 0];
            const float v1 = acc[nt][h * 2 + 1];
            if (isA) {
                const size_t idx = (size_t)grow * KK + col;
                *reinterpret_cast<__half2*>(g_Ph + idx) =
                    __half2(__float2half(fmaxf(v0, 0.0f)), __float2half(fmaxf(v1, 0.0f)));
            } else {
                const size_t idx = (size_t)(grow - NA) * KK + col;
                *reinterpret_cast<__half2*>(g_Mb + idx) =
                    __half2(__float2half(v0 <= 0.0f ? 1.0f : 0.0f),
                            __float2half(v1 <= 0.0f ? 1.0f : 0.0f));
            }
        }
}

// ---------------------------------------------------------------------------
// Stage 2: out[1024x1024] = Ph · Mb^T (fp16, fp32 accum)
// Tile 64(M) x 128(N), 256 threads (8 warps 2x4, warp tile 32x32),
// k-chunk 64, 3 buffers, 1 sync/chunk. grid (8, 16).
// ---------------------------------------------------------------------------
constexpr uint32_t S2_BUF = 3 * ARR;    // Ph 64 rows (1 ARR) + Mb 128 rows (2 ARR)
constexpr int S2_SMEM = 3 * S2_BUF;     // 82944

__global__ __launch_bounds__(256) void stage2_mma(float* __restrict__ out)
{
    extern __shared__ char dsm[];
    const uint32_t sb = smem_u32(dsm);

    const int tid = threadIdx.x;
    const int lane = tid & 31;
    const int wid = tid >> 5;
    const int wm = wid & 1;          // 2 warp rows x 32
    const int wn = wid >> 1;         // 4 warp cols x 32

    const int i0 = blockIdx.y * 64;
    const int j0 = blockIdx.x * 128;

    const __half* pPh = g_Ph + (size_t)i0 * KK;
    const __half* pMb = g_Mb + (size_t)j0 * KK;

    const int lr = tid >> 3, ls = tid & 7;   // 32 rows x 8 slots per pass
    auto load_chunk = [&](int ch, uint32_t buf) {
        const int k0 = ch * 64;
#pragma unroll
        for (int pass = 0; pass < 2; pass++) {   // Ph: 64 rows
            const int r = lr + pass * 32;
            cp16(buf + (uint32_t)r * TSTR + (uint32_t)(ls << 4),
                 pPh + (size_t)r * KK + k0 + ls * 8);
        }
#pragma unroll
        for (int pass = 0; pass < 4; pass++) {   // Mb: 128 rows, at offset ARR
            const int r = lr + pass * 32;
            cp16(buf + ARR + (uint32_t)r * TSTR + (uint32_t)(ls << 4),
                 pMb + (size_t)r * KK + k0 + ls * 8);
        }
        cp_commit();
    };

    constexpr int NCH = KK / 64;   // 4
    load_chunk(0, sb);
    load_chunk(1, sb + S2_BUF);

    float acc[2][4][4] = {};

    for (int ch = 0; ch < NCH; ch++) {
        if (ch + 1 < NCH) cp_wait1(); else cp_wait0();
        __syncthreads();
        if (ch + 2 < NCH) load_chunk(ch + 2, sb + (uint32_t)((ch + 2) % 3) * S2_BUF);

        const uint32_t bb = sb + (uint32_t)(ch % 3) * S2_BUF;
#pragma unroll
        for (int ks = 0; ks < 4; ks++) {
            const int koff = ks * 32;
            uint32_t ph[2][4], mb[2][4];
#pragma unroll
            for (int mt = 0; mt < 2; mt++)
                ldm_x4(ph[mt], a_addr(bb, wm * 32 + mt * 16, lane, koff));
#pragma unroll
            for (int p = 0; p < 2; p++)
                ldm_x4(mb[p], b_addr(bb + ARR, wn * 32 + p * 16, lane, koff));
#pragma unroll
            for (int mt = 0; mt < 2; mt++)
#pragma unroll
                for (int nt = 0; nt < 4; nt++)
                    mma_f16(acc[mt][nt], ph[mt], &mb[nt >> 1][(nt & 1) * 2]);
        }
    }

#pragma unroll
    for (int mt = 0; mt < 2; mt++)
#pragma unroll
        for (int nt = 0; nt < 4; nt++)
#pragma unroll
            for (int h = 0; h < 2; h++) {
                const int row = i0 + wm * 32 + mt * 16 + (lane >> 2) + h * 8;
                const int col = j0 + wn * 32 + nt * 8 + (lane & 3) * 2;
                *reinterpret_cast<float2*>(out + (size_t)row * NB + col) =
                    make_float2(acc[mt][nt][h * 2 + 0], acc[mt][nt][h * 2 + 1]);
            }
}

// ---------------------------------------------------------------------------
extern "C" void kernel_launch(void* const* d_in, const int* in_sizes, int n_in,
                              void* d_out, int out_size)
{
    const float* a     = (const float*)d_in[0];
    const float* b     = (const float*)d_in[1];
    const float* feats = (const float*)d_in[2];
    float* out = (float*)d_out;
    (void)in_sizes; (void)n_in; (void)out_size;

    cudaFuncSetAttribute(stage1_mma, cudaFuncAttributeMaxDynamicSharedMemorySize, S1_SMEM);
    cudaFuncSetAttribute(stage2_mma, cudaFuncAttributeMaxDynamicSharedMemorySize, S2_SMEM);

    convert_kernel<<<576, 256>>>(a, b, feats);
    stage1_mma<<<dim3(4, 32), 256, S1_SMEM>>>();
    stage2_mma<<<dim3(8, 16), 256, S2_SMEM>>>(out);
}